// round 1
// baseline (speedup 1.0000x reference)
#include <cuda_runtime.h>
#include <cuda_bf16.h>
#include <cstdint>

// Problem constants
#define B_  4
#define S_  2048
#define C_  1024
#define H_  16
#define D_  64
#define M_  (B_ * S_)      // 8192 tokens

// Scratch (allocation-free rule: __device__ globals)
__device__ float g_qkv[(size_t)M_ * 3 * C_];   // [M, 3C] = 96 MB
__device__ float g_att[(size_t)M_ * C_];       // [M, C]  = 32 MB

// ---------------------------------------------------------------------------
// SGEMM: C[m][n] = sum_k A[m][k] * W[n][k] + bias[n]
// A: [M,K] row-major, W: [N,K] row-major (torch Linear weight), C: [M,N]
// 128x128 tile, BK=8, 256 threads, 8x8 microtile with 4+4 split fragments.
// ---------------------------------------------------------------------------
__global__ __launch_bounds__(256) void sgemm_tn(
    const float* __restrict__ A, const float* __restrict__ W,
    const float* __restrict__ bias, float* __restrict__ Cmat,
    int M, int N, int K)
{
    __shared__ float As[8][128];
    __shared__ float Bs[8][128];

    const int tid  = threadIdx.x;
    const int brow = blockIdx.y * 128;
    const int bcol = blockIdx.x * 128;

    const int lrow = tid >> 1;           // 0..127
    const int lcol = (tid & 1) << 2;     // 0 or 4
    const int ty   = tid >> 4;           // 0..15
    const int tx   = tid & 15;           // 0..15

    const float* Aptr = A + (size_t)(brow + lrow) * K + lcol;
    const float* Wptr = W + (size_t)(bcol + lrow) * K + lcol;

    float acc[8][8];
#pragma unroll
    for (int i = 0; i < 8; i++)
#pragma unroll
        for (int j = 0; j < 8; j++) acc[i][j] = 0.f;

    for (int k0 = 0; k0 < K; k0 += 8) {
        float4 av = *(const float4*)(Aptr + k0);
        float4 wv = *(const float4*)(Wptr + k0);
        __syncthreads();   // previous compute done before overwriting smem
        As[lcol + 0][lrow] = av.x;
        As[lcol + 1][lrow] = av.y;
        As[lcol + 2][lrow] = av.z;
        As[lcol + 3][lrow] = av.w;
        Bs[lcol + 0][lrow] = wv.x;
        Bs[lcol + 1][lrow] = wv.y;
        Bs[lcol + 2][lrow] = wv.z;
        Bs[lcol + 3][lrow] = wv.w;
        __syncthreads();

#pragma unroll
        for (int kk = 0; kk < 8; kk++) {
            float af[8], bf[8];
            *(float4*)&af[0] = *(const float4*)&As[kk][ty * 4];
            *(float4*)&af[4] = *(const float4*)&As[kk][64 + ty * 4];
            *(float4*)&bf[0] = *(const float4*)&Bs[kk][tx * 4];
            *(float4*)&bf[4] = *(const float4*)&Bs[kk][64 + tx * 4];
#pragma unroll
            for (int i = 0; i < 8; i++)
#pragma unroll
                for (int j = 0; j < 8; j++)
                    acc[i][j] += af[i] * bf[j];
        }
    }

    // epilogue with bias
#pragma unroll
    for (int i = 0; i < 8; i++) {
        int row = brow + ((i < 4) ? (ty * 4 + i) : (64 + ty * 4 + (i - 4)));
#pragma unroll
        for (int jh = 0; jh < 2; jh++) {
            int col = bcol + jh * 64 + tx * 4;
            float4 o;
            o.x = acc[i][jh * 4 + 0] + bias[col + 0];
            o.y = acc[i][jh * 4 + 1] + bias[col + 1];
            o.z = acc[i][jh * 4 + 2] + bias[col + 2];
            o.w = acc[i][jh * 4 + 3] + bias[col + 3];
            *(float4*)&Cmat[(size_t)row * N + col] = o;
        }
    }
}

// ---------------------------------------------------------------------------
// Flash attention (causal), fp32.
// Grid: (S/64, B*H). Block: 256 threads.
// Mapping: quad per query row. tid = g*4 + t; g = query row in tile (0..63),
// t = 16-wide D-slice (0..3). Scores quad-reduced via shfl_xor; exp'ed P held
// in registers (16 per lane, lane t owns n with n&3==t) and broadcast with
// width-4 shfl during the PV accumulation. Online softmax per row.
// ---------------------------------------------------------------------------
__global__ __launch_bounds__(256) void attn_kernel(
    const float* __restrict__ qkv, float* __restrict__ out)
{
    __shared__ float Ks[64][68];   // [n][k]
    __shared__ float Vs[64][68];   // [n][d]

    const int qblk = blockIdx.x;          // 0..31
    const int bh   = blockIdx.y;          // 0..63
    const int b    = bh >> 4;
    const int h    = bh & 15;

    const int tid = threadIdx.x;
    const int g   = tid >> 2;             // query row in tile
    const int t   = tid & 3;              // dim slice
    const int qi  = qblk * 64 + g;        // global query index

    const float* base = qkv + (size_t)b * S_ * 3 * C_;

    // Load Q row slice, pre-scaled by 1/sqrt(D)
    float q[16];
    {
        const float* qrow = base + (size_t)qi * (3 * C_) + h * 64 + 16 * t;
#pragma unroll
        for (int j = 0; j < 16; j++) q[j] = qrow[j] * 0.125f;
    }

    float O[16];
#pragma unroll
    for (int j = 0; j < 16; j++) O[j] = 0.f;
    float m_i = -1e30f, l_i = 0.f;

    for (int kvb = 0; kvb <= qblk; kvb++) {
        __syncthreads();   // previous tile's compute done
        // Load K and V tiles (64 rows x 64 cols each): 4 float4 per thread each
#pragma unroll
        for (int r = 0; r < 4; r++) {
            int idx = r * 256 + tid;
            int n = idx >> 4;
            int c = (idx & 15) << 2;
            const float* kp = base + (size_t)(kvb * 64 + n) * (3 * C_) + C_ + h * 64 + c;
            const float* vp = base + (size_t)(kvb * 64 + n) * (3 * C_) + 2 * C_ + h * 64 + c;
            *(float4*)&Ks[n][c] = *(const float4*)kp;
            *(float4*)&Vs[n][c] = *(const float4*)vp;
        }
        __syncthreads();

        // Scores: s[n] = q . K[n]  (quad-reduced)
        float s[16];
        float m_tile = -1e30f;
        const bool diag = (kvb == qblk);
#pragma unroll
        for (int n = 0; n < 64; n++) {
            float acc = 0.f;
            const float* kr = &Ks[n][16 * t];
#pragma unroll
            for (int j = 0; j < 16; j++) acc += q[j] * kr[j];
            acc += __shfl_xor_sync(0xffffffffu, acc, 1);
            acc += __shfl_xor_sync(0xffffffffu, acc, 2);
            if (diag && (kvb * 64 + n) > qi) acc = -1e30f;
            if ((n & 3) == t) s[n >> 2] = acc;
            m_tile = fmaxf(m_tile, acc);
        }

        const float m_new = fmaxf(m_i, m_tile);
        const float alpha = __expf(m_i - m_new);
        float lsum = 0.f;
#pragma unroll
        for (int nn = 0; nn < 16; nn++) {
            s[nn] = __expf(s[nn] - m_new);
            lsum += s[nn];
        }
        lsum += __shfl_xor_sync(0xffffffffu, lsum, 1);
        lsum += __shfl_xor_sync(0xffffffffu, lsum, 2);
        l_i = l_i * alpha + lsum;
        m_i = m_new;
#pragma unroll
        for (int j = 0; j < 16; j++) O[j] *= alpha;

        // PV accumulation
#pragma unroll
        for (int nn = 0; nn < 16; nn++) {
#pragma unroll
            for (int nq = 0; nq < 4; nq++) {
                const int n = nn * 4 + nq;
                float p = __shfl_sync(0xffffffffu, s[nn], nq, 4);
                const float* vr = &Vs[n][16 * t];
#pragma unroll
                for (int j = 0; j < 16; j++) O[j] += p * vr[j];
            }
        }
    }

    // Normalize and write: out is [B,S,C] with head h at cols h*64..h*64+63
    const float inv_l = 1.f / l_i;
    float* orow = out + (size_t)(b * S_ + qi) * C_ + h * 64 + 16 * t;
#pragma unroll
    for (int jj = 0; jj < 4; jj++) {
        float4 o;
        o.x = O[jj * 4 + 0] * inv_l;
        o.y = O[jj * 4 + 1] * inv_l;
        o.z = O[jj * 4 + 2] * inv_l;
        o.w = O[jj * 4 + 3] * inv_l;
        *(float4*)&orow[jj * 4] = o;
    }
}

// ---------------------------------------------------------------------------
extern "C" void kernel_launch(void* const* d_in, const int* in_sizes, int n_in,
                              void* d_out, int out_size)
{
    const float* x      = (const float*)d_in[0];
    const float* qkv_w  = (const float*)d_in[1];
    const float* qkv_b  = (const float*)d_in[2];
    const float* proj_w = (const float*)d_in[3];
    const float* proj_b = (const float*)d_in[4];
    float* out = (float*)d_out;

    float *qkv, *att;
    cudaGetSymbolAddress((void**)&qkv, g_qkv);
    cudaGetSymbolAddress((void**)&att, g_att);

    // QKV: [8192,1024] x [3072,1024]^T
    sgemm_tn<<<dim3(3072 / 128, M_ / 128), 256>>>(x, qkv_w, qkv_b, qkv,
                                                  M_, 3 * C_, C_);
    // Attention
    attn_kernel<<<dim3(S_ / 64, B_ * H_), 256>>>(qkv, att);
    // Proj: [8192,1024] x [1024,1024]^T
    sgemm_tn<<<dim3(C_ / 128, M_ / 128), 256>>>(att, proj_w, proj_b, out,
                                                M_, C_, C_);
}

// round 3
// speedup vs baseline: 6.6634x; 6.6634x over previous
#include <cuda_runtime.h>
#include <cuda_bf16.h>
#include <cstdint>

// Problem constants
#define B_  4
#define S_  2048
#define C_  1024
#define H_  16
#define D_  64
#define M_  (B_ * S_)      // 8192 tokens

// Scratch (allocation-free rule: __device__ globals)
__device__ float g_qkv[(size_t)M_ * 3 * C_];   // [M, 3C] = 96 MB
__device__ float g_att[(size_t)M_ * C_];       // [M, C]  = 32 MB

// ---------------------------------------------------------------------------
// Helpers: tf32 convert + m16n8k8 tf32 MMA
// ---------------------------------------------------------------------------
__device__ __forceinline__ uint32_t to_tf32(float x) {
    uint32_t r;
    asm("cvt.rna.tf32.f32 %0, %1;" : "=r"(r) : "f"(x));
    return r;
}

__device__ __forceinline__ void mma_tf32(float& c0, float& c1, float& c2, float& c3,
                                         uint32_t a0, uint32_t a1, uint32_t a2, uint32_t a3,
                                         uint32_t b0, uint32_t b1) {
    asm volatile(
        "mma.sync.aligned.m16n8k8.row.col.f32.tf32.tf32.f32 "
        "{%0,%1,%2,%3}, {%4,%5,%6,%7}, {%8,%9}, {%0,%1,%2,%3};\n"
        : "+f"(c0), "+f"(c1), "+f"(c2), "+f"(c3)
        : "r"(a0), "r"(a1), "r"(a2), "r"(a3), "r"(b0), "r"(b1));
}

// ---------------------------------------------------------------------------
// TF32 GEMM: C[m][n] = sum_k A[m][k]*W[n][k] + bias[n]
// A:[M,K] rm, W:[N,K] rm. 128x128x16 tile, 256 thr, warp tile 32x64.
// ---------------------------------------------------------------------------
__global__ __launch_bounds__(256) void gemm_tf32(
    const float* __restrict__ A, const float* __restrict__ W,
    const float* __restrict__ bias, float* __restrict__ Cmat,
    int M, int N, int K)
{
    __shared__ float As[128][20];
    __shared__ float Bs[128][20];

    const int tid  = threadIdx.x;
    const int lane = tid & 31;
    const int warp = tid >> 5;
    const int m_off = (warp >> 1) * 32;   // 4 warp rows
    const int n_off = (warp & 1) * 64;    // 2 warp cols
    const int brow = blockIdx.y * 128;
    const int bcol = blockIdx.x * 128;

    const int gr  = lane >> 2;            // 0..7 (groupID)
    const int gc  = lane & 3;             // 0..3 (threadID_in_group)

    float acc[2][8][4];
#pragma unroll
    for (int mi = 0; mi < 2; mi++)
#pragma unroll
        for (int ni = 0; ni < 8; ni++)
#pragma unroll
            for (int c = 0; c < 4; c++) acc[mi][ni][c] = 0.f;

    // per-thread global addresses: idx = i*256 + tid; row = idx>>2, c4 = (idx&3)*4
    int rowA[2], c4A[2];
#pragma unroll
    for (int i = 0; i < 2; i++) {
        int idx = i * 256 + tid;
        rowA[i] = idx >> 2;
        c4A[i]  = (idx & 3) << 2;
    }

    float4 pa[2], pb[2];
#pragma unroll
    for (int i = 0; i < 2; i++) {
        pa[i] = *(const float4*)(A + (size_t)(brow + rowA[i]) * K + c4A[i]);
        pb[i] = *(const float4*)(W + (size_t)(bcol + rowA[i]) * K + c4A[i]);
    }

    for (int k0 = 0; k0 < K; k0 += 16) {
        __syncthreads();
#pragma unroll
        for (int i = 0; i < 2; i++) {
            As[rowA[i]][c4A[i] + 0] = __uint_as_float(to_tf32(pa[i].x));
            As[rowA[i]][c4A[i] + 1] = __uint_as_float(to_tf32(pa[i].y));
            As[rowA[i]][c4A[i] + 2] = __uint_as_float(to_tf32(pa[i].z));
            As[rowA[i]][c4A[i] + 3] = __uint_as_float(to_tf32(pa[i].w));
            Bs[rowA[i]][c4A[i] + 0] = __uint_as_float(to_tf32(pb[i].x));
            Bs[rowA[i]][c4A[i] + 1] = __uint_as_float(to_tf32(pb[i].y));
            Bs[rowA[i]][c4A[i] + 2] = __uint_as_float(to_tf32(pb[i].z));
            Bs[rowA[i]][c4A[i] + 3] = __uint_as_float(to_tf32(pb[i].w));
        }
        __syncthreads();

        // prefetch next slab
        if (k0 + 16 < K) {
#pragma unroll
            for (int i = 0; i < 2; i++) {
                pa[i] = *(const float4*)(A + (size_t)(brow + rowA[i]) * K + k0 + 16 + c4A[i]);
                pb[i] = *(const float4*)(W + (size_t)(bcol + rowA[i]) * K + k0 + 16 + c4A[i]);
            }
        }

#pragma unroll
        for (int kk = 0; kk < 16; kk += 8) {
            uint32_t af[2][4];
#pragma unroll
            for (int mi = 0; mi < 2; mi++) {
                int r = m_off + 16 * mi + gr;
                af[mi][0] = __float_as_uint(As[r    ][kk + gc    ]);
                af[mi][1] = __float_as_uint(As[r + 8][kk + gc    ]);
                af[mi][2] = __float_as_uint(As[r    ][kk + gc + 4]);
                af[mi][3] = __float_as_uint(As[r + 8][kk + gc + 4]);
            }
            uint32_t bf[8][2];
#pragma unroll
            for (int ni = 0; ni < 8; ni++) {
                int n = n_off + 8 * ni + gr;
                bf[ni][0] = __float_as_uint(Bs[n][kk + gc    ]);
                bf[ni][1] = __float_as_uint(Bs[n][kk + gc + 4]);
            }
#pragma unroll
            for (int mi = 0; mi < 2; mi++)
#pragma unroll
                for (int ni = 0; ni < 8; ni++)
                    mma_tf32(acc[mi][ni][0], acc[mi][ni][1], acc[mi][ni][2], acc[mi][ni][3],
                             af[mi][0], af[mi][1], af[mi][2], af[mi][3],
                             bf[ni][0], bf[ni][1]);
        }
    }

    // epilogue: c0,c1 -> (row, 2gc..+1), c2,c3 -> (row+8, ..)
#pragma unroll
    for (int mi = 0; mi < 2; mi++) {
        int r0 = brow + m_off + 16 * mi + gr;
#pragma unroll
        for (int ni = 0; ni < 8; ni++) {
            int col = bcol + n_off + 8 * ni + 2 * gc;
            float2 o0, o1;
            o0.x = acc[mi][ni][0] + bias[col];
            o0.y = acc[mi][ni][1] + bias[col + 1];
            o1.x = acc[mi][ni][2] + bias[col];
            o1.y = acc[mi][ni][3] + bias[col + 1];
            *(float2*)&Cmat[(size_t)r0 * N + col]       = o0;
            *(float2*)&Cmat[(size_t)(r0 + 8) * N + col] = o1;
        }
    }
}

// ---------------------------------------------------------------------------
// Flash attention (causal), tf32 MMA. Grid (32, 64), block 128 (4 warps).
// Warp w: 16 Q rows. QK^T and PV both m16n8k8 tf32; P stays in registers
// (C-frag -> A-frag permute via quad shuffles). Qs aliases Ks.
// ---------------------------------------------------------------------------
__global__ __launch_bounds__(128) void attn_tf32(
    const float* __restrict__ qkv, float* __restrict__ out)
{
    __shared__ float Ks[64][76];   // [kv][d]
    __shared__ float Vs[64][72];   // [kv][d]

    const int qblk = gridDim.x - 1 - blockIdx.x;   // long blocks first
    const int bh   = blockIdx.y;
    const int b    = bh >> 4;
    const int h    = bh & 15;

    const int tid  = threadIdx.x;
    const int lane = tid & 31;
    const int w    = tid >> 5;
    const int gr   = lane >> 2;     // 0..7
    const int gc   = lane & 3;      // 0..3

    const float* base = qkv + (size_t)b * S_ * 3 * C_;

    // ---- Load Q tile into smem (aliased onto Ks), build A-frags ----
    // 64x64 floats = 1024 float4; 128 threads -> 8 iterations.
    {
#pragma unroll
        for (int i = 0; i < 8; i++) {
            int idx = i * 128 + tid;
            int r = idx >> 4;
            int c = (idx & 15) << 2;
            float4 qv = *(const float4*)(base + (size_t)(qblk * 64 + r) * (3 * C_) + h * 64 + c);
            Ks[r][c + 0] = __uint_as_float(to_tf32(qv.x * 0.125f));
            Ks[r][c + 1] = __uint_as_float(to_tf32(qv.y * 0.125f));
            Ks[r][c + 2] = __uint_as_float(to_tf32(qv.z * 0.125f));
            Ks[r][c + 3] = __uint_as_float(to_tf32(qv.w * 0.125f));
        }
    }
    __syncthreads();

    uint32_t qf[8][4];
    {
        int r = 16 * w + gr;
#pragma unroll
        for (int kk = 0; kk < 8; kk++) {
            qf[kk][0] = __float_as_uint(Ks[r    ][8 * kk + gc    ]);
            qf[kk][1] = __float_as_uint(Ks[r + 8][8 * kk + gc    ]);
            qf[kk][2] = __float_as_uint(Ks[r    ][8 * kk + gc + 4]);
            qf[kk][3] = __float_as_uint(Ks[r + 8][8 * kk + gc + 4]);
        }
    }

    float o[8][4];
#pragma unroll
    for (int j = 0; j < 8; j++)
#pragma unroll
        for (int c = 0; c < 4; c++) o[j][c] = 0.f;
    float m0 = -1e30f, m1 = -1e30f, l0 = 0.f, l1 = 0.f;

    const int row0 = qblk * 64 + 16 * w + gr;   // global q row (and +8)

    for (int kvb = 0; kvb <= qblk; kvb++) {
        __syncthreads();   // prior tile compute done (also protects Qs->Ks)
        // load K and V tiles with tf32 convert: 8 float4 iterations each
#pragma unroll
        for (int i = 0; i < 8; i++) {
            int idx = i * 128 + tid;
            int r = idx >> 4;
            int c = (idx & 15) << 2;
            const float* kp = base + (size_t)(kvb * 64 + r) * (3 * C_) + C_ + h * 64 + c;
            const float* vp = base + (size_t)(kvb * 64 + r) * (3 * C_) + 2 * C_ + h * 64 + c;
            float4 kv4 = *(const float4*)kp;
            float4 vv4 = *(const float4*)vp;
            Ks[r][c + 0] = __uint_as_float(to_tf32(kv4.x));
            Ks[r][c + 1] = __uint_as_float(to_tf32(kv4.y));
            Ks[r][c + 2] = __uint_as_float(to_tf32(kv4.z));
            Ks[r][c + 3] = __uint_as_float(to_tf32(kv4.w));
            Vs[r][c + 0] = __uint_as_float(to_tf32(vv4.x));
            Vs[r][c + 1] = __uint_as_float(to_tf32(vv4.y));
            Vs[r][c + 2] = __uint_as_float(to_tf32(vv4.z));
            Vs[r][c + 3] = __uint_as_float(to_tf32(vv4.w));
        }
        __syncthreads();

        // ---- S = Q K^T (16x64 per warp) ----
        float s[8][4];
#pragma unroll
        for (int j = 0; j < 8; j++)
#pragma unroll
            for (int c = 0; c < 4; c++) s[j][c] = 0.f;

#pragma unroll
        for (int j = 0; j < 8; j++) {        // kv n-tiles
            int n = 8 * j + gr;
#pragma unroll
            for (int kk = 0; kk < 8; kk++) { // d k-steps
                uint32_t b0 = __float_as_uint(Ks[n][8 * kk + gc]);
                uint32_t b1 = __float_as_uint(Ks[n][8 * kk + gc + 4]);
                mma_tf32(s[j][0], s[j][1], s[j][2], s[j][3],
                         qf[kk][0], qf[kk][1], qf[kk][2], qf[kk][3], b0, b1);
            }
        }

        // ---- mask (diagonal tile) ----
        if (kvb == qblk) {
#pragma unroll
            for (int j = 0; j < 8; j++) {
                int colb = kvb * 64 + 8 * j + 2 * gc;
                if (colb     > row0)     s[j][0] = -1e30f;
                if (colb + 1 > row0)     s[j][1] = -1e30f;
                if (colb     > row0 + 8) s[j][2] = -1e30f;
                if (colb + 1 > row0 + 8) s[j][3] = -1e30f;
            }
        }

        // ---- online softmax ----
        float mt0 = -1e30f, mt1 = -1e30f;
#pragma unroll
        for (int j = 0; j < 8; j++) {
            mt0 = fmaxf(mt0, fmaxf(s[j][0], s[j][1]));
            mt1 = fmaxf(mt1, fmaxf(s[j][2], s[j][3]));
        }
        mt0 = fmaxf(mt0, __shfl_xor_sync(0xffffffffu, mt0, 1));
        mt0 = fmaxf(mt0, __shfl_xor_sync(0xffffffffu, mt0, 2));
        mt1 = fmaxf(mt1, __shfl_xor_sync(0xffffffffu, mt1, 1));
        mt1 = fmaxf(mt1, __shfl_xor_sync(0xffffffffu, mt1, 2));

        const float mn0 = fmaxf(m0, mt0);
        const float mn1 = fmaxf(m1, mt1);
        const float al0 = __expf(m0 - mn0);
        const float al1 = __expf(m1 - mn1);
        float ls0 = 0.f, ls1 = 0.f;
#pragma unroll
        for (int j = 0; j < 8; j++) {
            s[j][0] = __expf(s[j][0] - mn0);
            s[j][1] = __expf(s[j][1] - mn0);
            s[j][2] = __expf(s[j][2] - mn1);
            s[j][3] = __expf(s[j][3] - mn1);
            ls0 += s[j][0] + s[j][1];
            ls1 += s[j][2] + s[j][3];
        }
        ls0 += __shfl_xor_sync(0xffffffffu, ls0, 1);
        ls0 += __shfl_xor_sync(0xffffffffu, ls0, 2);
        ls1 += __shfl_xor_sync(0xffffffffu, ls1, 1);
        ls1 += __shfl_xor_sync(0xffffffffu, ls1, 2);
        l0 = l0 * al0 + ls0;
        l1 = l1 * al1 + ls1;
        m0 = mn0;
        m1 = mn1;
#pragma unroll
        for (int j = 0; j < 8; j++) {
            o[j][0] *= al0; o[j][1] *= al0;
            o[j][2] *= al1; o[j][3] *= al1;
        }

        // ---- PV: O += P V ----
        const int qs = gc >> 1;     // source quad-lane (0/1)
        const int sel = gc & 1;
#pragma unroll
        for (int kk = 0; kk < 8; kk++) {   // S n-tile kk == PV k-step
            uint32_t p0 = to_tf32(s[kk][0]);
            uint32_t p1 = to_tf32(s[kk][1]);
            uint32_t p2 = to_tf32(s[kk][2]);
            uint32_t p3 = to_tf32(s[kk][3]);
            // C-frag -> A-frag permute (quad shuffles)
            uint32_t t0 = __shfl_sync(0xffffffffu, p0, qs, 4);
            uint32_t t1 = __shfl_sync(0xffffffffu, p1, qs, 4);
            uint32_t t2 = __shfl_sync(0xffffffffu, p0, 2 + qs, 4);
            uint32_t t3 = __shfl_sync(0xffffffffu, p1, 2 + qs, 4);
            uint32_t u0 = __shfl_sync(0xffffffffu, p2, qs, 4);
            uint32_t u1 = __shfl_sync(0xffffffffu, p3, qs, 4);
            uint32_t u2 = __shfl_sync(0xffffffffu, p2, 2 + qs, 4);
            uint32_t u3 = __shfl_sync(0xffffffffu, p3, 2 + qs, 4);
            uint32_t a0 = sel ? t1 : t0;
            uint32_t a2 = sel ? t3 : t2;
            uint32_t a1 = sel ? u1 : u0;
            uint32_t a3 = sel ? u3 : u2;
#pragma unroll
            for (int j2 = 0; j2 < 8; j2++) {   // d n-tiles
                uint32_t b0 = __float_as_uint(Vs[8 * kk + gc    ][8 * j2 + gr]);
                uint32_t b1 = __float_as_uint(Vs[8 * kk + gc + 4][8 * j2 + gr]);
                mma_tf32(o[j2][0], o[j2][1], o[j2][2], o[j2][3],
                         a0, a1, a2, a3, b0, b1);
            }
        }
    }

    // ---- normalize + write ----
    const float il0 = 1.f / l0;
    const float il1 = 1.f / l1;
    float* op0 = out + (size_t)(b * S_ + row0) * C_ + h * 64;
    float* op1 = out + (size_t)(b * S_ + row0 + 8) * C_ + h * 64;
#pragma unroll
    for (int j2 = 0; j2 < 8; j2++) {
        int d0 = 8 * j2 + 2 * gc;
        float2 w0, w1;
        w0.x = o[j2][0] * il0; w0.y = o[j2][1] * il0;
        w1.x = o[j2][2] * il1; w1.y = o[j2][3] * il1;
        *(float2*)&op0[d0] = w0;
        *(float2*)&op1[d0] = w1;
    }
}

// ---------------------------------------------------------------------------
extern "C" void kernel_launch(void* const* d_in, const int* in_sizes, int n_in,
                              void* d_out, int out_size)
{
    const float* x      = (const float*)d_in[0];
    const float* qkv_w  = (const float*)d_in[1];
    const float* qkv_b  = (const float*)d_in[2];
    const float* proj_w = (const float*)d_in[3];
    const float* proj_b = (const float*)d_in[4];
    float* out = (float*)d_out;

    float *qkv, *att;
    cudaGetSymbolAddress((void**)&qkv, g_qkv);
    cudaGetSymbolAddress((void**)&att, g_att);

    // QKV: [8192,1024] x [3072,1024]^T
    gemm_tf32<<<dim3(3072 / 128, M_ / 128), 256>>>(x, qkv_w, qkv_b, qkv,
                                                   M_, 3 * C_, C_);
    // Attention
    attn_tf32<<<dim3(S_ / 64, B_ * H_), 128>>>(qkv, att);
    // Proj: [8192,1024] x [1024,1024]^T
    gemm_tf32<<<dim3(C_ / 128, M_ / 128), 256>>>(att, proj_w, proj_b, out,
                                                 M_, C_, C_);
}

// round 4
// speedup vs baseline: 13.0364x; 1.9564x over previous
#include <cuda_runtime.h>
#include <cuda_fp16.h>
#include <cstdint>

// Problem constants
#define B_  4
#define S_  2048
#define C_  1024
#define H_  16
#define D_  64
#define M_  (B_ * S_)      // 8192 tokens

// Scratch (allocation-free rule: __device__ globals)
__device__ float g_qkv[(size_t)M_ * 3 * C_];   // [M, 3C] = 96 MB
__device__ float g_att[(size_t)M_ * C_];       // [M, C]  = 32 MB

// ---------------------------------------------------------------------------
// Helpers
// ---------------------------------------------------------------------------
__device__ __forceinline__ uint32_t pack_h2(float x, float y) {
    __half2 h = __floats2half2_rn(x, y);
    return *reinterpret_cast<uint32_t*>(&h);
}

__device__ __forceinline__ void mma_f16(float& c0, float& c1, float& c2, float& c3,
                                        uint32_t a0, uint32_t a1, uint32_t a2, uint32_t a3,
                                        uint32_t b0, uint32_t b1) {
    asm volatile(
        "mma.sync.aligned.m16n8k16.row.col.f32.f16.f16.f32 "
        "{%0,%1,%2,%3}, {%4,%5,%6,%7}, {%8,%9}, {%0,%1,%2,%3};\n"
        : "+f"(c0), "+f"(c1), "+f"(c2), "+f"(c3)
        : "r"(a0), "r"(a1), "r"(a2), "r"(a3), "r"(b0), "r"(b1));
}

__device__ __forceinline__ void ldsm_x4(uint32_t& r0, uint32_t& r1, uint32_t& r2, uint32_t& r3,
                                        uint32_t addr) {
    asm volatile("ldmatrix.sync.aligned.m8n8.x4.shared.b16 {%0,%1,%2,%3}, [%4];\n"
                 : "=r"(r0), "=r"(r1), "=r"(r2), "=r"(r3) : "r"(addr));
}

__device__ __forceinline__ void ldsm_x4_trans(uint32_t& r0, uint32_t& r1, uint32_t& r2, uint32_t& r3,
                                              uint32_t addr) {
    asm volatile("ldmatrix.sync.aligned.m8n8.x4.trans.shared.b16 {%0,%1,%2,%3}, [%4];\n"
                 : "=r"(r0), "=r"(r1), "=r"(r2), "=r"(r3) : "r"(addr));
}

// ---------------------------------------------------------------------------
// FP16 GEMM: C[m][n] = sum_k A[m][k]*W[n][k] + bias[n]
// A:[M,K] f32 rm, W:[N,K] f32 rm. 128x128x32 tile, 256 thr, warp tile 32x64.
// Smem stride 40 halves (80 B): ldmatrix row addrs hit 8 distinct bank groups.
// ---------------------------------------------------------------------------
__global__ __launch_bounds__(256) void gemm_f16(
    const float* __restrict__ A, const float* __restrict__ W,
    const float* __restrict__ bias, float* __restrict__ Cmat,
    int M, int N, int K)
{
    __shared__ __half As[128][40];
    __shared__ __half Bs[128][40];

    const int tid  = threadIdx.x;
    const int lane = tid & 31;
    const int warp = tid >> 5;
    const int m_off = (warp >> 1) * 32;   // 4 warp rows
    const int n_off = (warp & 1) * 64;    // 2 warp cols
    const int brow = blockIdx.y * 128;
    const int bcol = blockIdx.x * 128;

    const int gr = lane >> 2;
    const int gc = lane & 3;

    float acc[2][8][4];
#pragma unroll
    for (int mi = 0; mi < 2; mi++)
#pragma unroll
        for (int ni = 0; ni < 8; ni++)
#pragma unroll
            for (int c = 0; c < 4; c++) acc[mi][ni][c] = 0.f;

    // global loads: 128x32 f32 = 1024 float4 per matrix; 4 per thread
    int rowL[4], c4L[4];
#pragma unroll
    for (int i = 0; i < 4; i++) {
        int idx = i * 256 + tid;
        rowL[i] = idx >> 3;
        c4L[i]  = (idx & 7) << 2;
    }

    // ldmatrix lane-address components
    const int lrow8 = ((lane >> 3) & 1) * 8 + (lane & 7);
    const int lhi8  = ((lane >> 4) & 1) * 8;
    const uint32_t as_base = (uint32_t)__cvta_generic_to_shared(&As[0][0]);
    const uint32_t bs_base = (uint32_t)__cvta_generic_to_shared(&Bs[0][0]);

    float4 pa[4], pb[4];
#pragma unroll
    for (int i = 0; i < 4; i++) {
        pa[i] = *(const float4*)(A + (size_t)(brow + rowL[i]) * K + c4L[i]);
        pb[i] = *(const float4*)(W + (size_t)(bcol + rowL[i]) * K + c4L[i]);
    }

    for (int k0 = 0; k0 < K; k0 += 32) {
        __syncthreads();
#pragma unroll
        for (int i = 0; i < 4; i++) {
            *(__half2*)&As[rowL[i]][c4L[i]]     = __floats2half2_rn(pa[i].x, pa[i].y);
            *(__half2*)&As[rowL[i]][c4L[i] + 2] = __floats2half2_rn(pa[i].z, pa[i].w);
            *(__half2*)&Bs[rowL[i]][c4L[i]]     = __floats2half2_rn(pb[i].x, pb[i].y);
            *(__half2*)&Bs[rowL[i]][c4L[i] + 2] = __floats2half2_rn(pb[i].z, pb[i].w);
        }
        __syncthreads();

        if (k0 + 32 < K) {
#pragma unroll
            for (int i = 0; i < 4; i++) {
                pa[i] = *(const float4*)(A + (size_t)(brow + rowL[i]) * K + k0 + 32 + c4L[i]);
                pb[i] = *(const float4*)(W + (size_t)(bcol + rowL[i]) * K + k0 + 32 + c4L[i]);
            }
        }

#pragma unroll
        for (int kk = 0; kk < 2; kk++) {
            uint32_t af[2][4];
#pragma unroll
            for (int mi = 0; mi < 2; mi++) {
                uint32_t addr = as_base +
                    ((uint32_t)(m_off + 16 * mi + lrow8) * 40u + kk * 16 + lhi8) * 2u;
                ldsm_x4(af[mi][0], af[mi][1], af[mi][2], af[mi][3], addr);
            }
            uint32_t bf[8][2];
#pragma unroll
            for (int c = 0; c < 4; c++) {
                // B: rows n, lanes 0-7 n0-7@k0, 8-15 n0-7@k8, 16-23 n8-15@k0, 24-31 n8-15@k8
                int nrow = n_off + c * 16 + lhi8 + (lane & 7);
                int kcol = kk * 16 + ((lane >> 3) & 1) * 8;
                uint32_t addr = bs_base + ((uint32_t)nrow * 40u + kcol) * 2u;
                ldsm_x4(bf[2 * c][0], bf[2 * c][1], bf[2 * c + 1][0], bf[2 * c + 1][1], addr);
            }
#pragma unroll
            for (int mi = 0; mi < 2; mi++)
#pragma unroll
                for (int ni = 0; ni < 8; ni++)
                    mma_f16(acc[mi][ni][0], acc[mi][ni][1], acc[mi][ni][2], acc[mi][ni][3],
                            af[mi][0], af[mi][1], af[mi][2], af[mi][3],
                            bf[ni][0], bf[ni][1]);
        }
    }

    // epilogue
#pragma unroll
    for (int mi = 0; mi < 2; mi++) {
        int r0 = brow + m_off + 16 * mi + gr;
#pragma unroll
        for (int ni = 0; ni < 8; ni++) {
            int col = bcol + n_off + 8 * ni + 2 * gc;
            float2 o0, o1;
            o0.x = acc[mi][ni][0] + bias[col];
            o0.y = acc[mi][ni][1] + bias[col + 1];
            o1.x = acc[mi][ni][2] + bias[col];
            o1.y = acc[mi][ni][3] + bias[col + 1];
            *(float2*)&Cmat[(size_t)r0 * N + col]       = o0;
            *(float2*)&Cmat[(size_t)(r0 + 8) * N + col] = o1;
        }
    }
}

// ---------------------------------------------------------------------------
// Flash attention (causal), fp16 MMA m16n8k16. Grid (32, 64), block 128.
// Warp w: 16 Q rows. P C-frag == fp16 A-frag layout (just pack half2).
// Smem stride 72 halves (144 B): conflict-free for both trans/non-trans LDSM.
// ---------------------------------------------------------------------------
__global__ __launch_bounds__(128) void attn_f16(
    const float* __restrict__ qkv, float* __restrict__ out)
{
    __shared__ __half Ks[64][72];   // K (and Q during prologue): [row][d]
    __shared__ __half Vs[64][72];   // V: [kv][d]

    const int qblk = gridDim.x - 1 - blockIdx.x;   // long blocks first
    const int bh   = blockIdx.y;
    const int b    = bh >> 4;
    const int h    = bh & 15;

    const int tid  = threadIdx.x;
    const int lane = tid & 31;
    const int w    = tid >> 5;
    const int gr   = lane >> 2;
    const int gc   = lane & 3;

    const int lrow8 = ((lane >> 3) & 1) * 8 + (lane & 7);
    const int lhi8  = ((lane >> 4) & 1) * 8;
    const uint32_t ks_base = (uint32_t)__cvta_generic_to_shared(&Ks[0][0]);
    const uint32_t vs_base = (uint32_t)__cvta_generic_to_shared(&Vs[0][0]);

    const float* base = qkv + (size_t)b * S_ * 3 * C_;

    // ---- Load Q tile into Ks (aliased), build A-frags ----
#pragma unroll
    for (int i = 0; i < 8; i++) {
        int idx = i * 128 + tid;
        int r = idx >> 4;
        int c = (idx & 15) << 2;
        float4 qv = *(const float4*)(base + (size_t)(qblk * 64 + r) * (3 * C_) + h * 64 + c);
        *(__half2*)&Ks[r][c]     = __floats2half2_rn(qv.x * 0.125f, qv.y * 0.125f);
        *(__half2*)&Ks[r][c + 2] = __floats2half2_rn(qv.z * 0.125f, qv.w * 0.125f);
    }
    __syncthreads();

    uint32_t qf[4][4];   // 4 k-steps of 16
#pragma unroll
    for (int kk = 0; kk < 4; kk++) {
        uint32_t addr = ks_base + ((uint32_t)(16 * w + lrow8) * 72u + kk * 16 + lhi8) * 2u;
        ldsm_x4(qf[kk][0], qf[kk][1], qf[kk][2], qf[kk][3], addr);
    }

    float o[8][4];
#pragma unroll
    for (int j = 0; j < 8; j++)
#pragma unroll
        for (int c = 0; c < 4; c++) o[j][c] = 0.f;
    float m0 = -1e30f, m1 = -1e30f, l0 = 0.f, l1 = 0.f;

    const int row0 = qblk * 64 + 16 * w + gr;

    for (int kvb = 0; kvb <= qblk; kvb++) {
        __syncthreads();
#pragma unroll
        for (int i = 0; i < 8; i++) {
            int idx = i * 128 + tid;
            int r = idx >> 4;
            int c = (idx & 15) << 2;
            const float* kp = base + (size_t)(kvb * 64 + r) * (3 * C_) + C_ + h * 64 + c;
            const float* vp = base + (size_t)(kvb * 64 + r) * (3 * C_) + 2 * C_ + h * 64 + c;
            float4 kv4 = *(const float4*)kp;
            float4 vv4 = *(const float4*)vp;
            *(__half2*)&Ks[r][c]     = __floats2half2_rn(kv4.x, kv4.y);
            *(__half2*)&Ks[r][c + 2] = __floats2half2_rn(kv4.z, kv4.w);
            *(__half2*)&Vs[r][c]     = __floats2half2_rn(vv4.x, vv4.y);
            *(__half2*)&Vs[r][c + 2] = __floats2half2_rn(vv4.z, vv4.w);
        }
        __syncthreads();

        // ---- S = Q K^T ----
        float s[8][4];
#pragma unroll
        for (int j = 0; j < 8; j++)
#pragma unroll
            for (int c = 0; c < 4; c++) s[j][c] = 0.f;

#pragma unroll
        for (int kk = 0; kk < 4; kk++) {
#pragma unroll
            for (int c = 0; c < 4; c++) {
                int nrow = c * 16 + lhi8 + (lane & 7);
                int kcol = kk * 16 + ((lane >> 3) & 1) * 8;
                uint32_t addr = ks_base + ((uint32_t)nrow * 72u + kcol) * 2u;
                uint32_t b00, b01, b10, b11;
                ldsm_x4(b00, b01, b10, b11, addr);
                mma_f16(s[2 * c][0], s[2 * c][1], s[2 * c][2], s[2 * c][3],
                        qf[kk][0], qf[kk][1], qf[kk][2], qf[kk][3], b00, b01);
                mma_f16(s[2 * c + 1][0], s[2 * c + 1][1], s[2 * c + 1][2], s[2 * c + 1][3],
                        qf[kk][0], qf[kk][1], qf[kk][2], qf[kk][3], b10, b11);
            }
        }

        // ---- mask (diagonal tile) ----
        if (kvb == qblk) {
#pragma unroll
            for (int j = 0; j < 8; j++) {
                int colb = kvb * 64 + 8 * j + 2 * gc;
                if (colb     > row0)     s[j][0] = -1e30f;
                if (colb + 1 > row0)     s[j][1] = -1e30f;
                if (colb     > row0 + 8) s[j][2] = -1e30f;
                if (colb + 1 > row0 + 8) s[j][3] = -1e30f;
            }
        }

        // ---- online softmax ----
        float mt0 = -1e30f, mt1 = -1e30f;
#pragma unroll
        for (int j = 0; j < 8; j++) {
            mt0 = fmaxf(mt0, fmaxf(s[j][0], s[j][1]));
            mt1 = fmaxf(mt1, fmaxf(s[j][2], s[j][3]));
        }
        mt0 = fmaxf(mt0, __shfl_xor_sync(0xffffffffu, mt0, 1));
        mt0 = fmaxf(mt0, __shfl_xor_sync(0xffffffffu, mt0, 2));
        mt1 = fmaxf(mt1, __shfl_xor_sync(0xffffffffu, mt1, 1));
        mt1 = fmaxf(mt1, __shfl_xor_sync(0xffffffffu, mt1, 2));

        const float mn0 = fmaxf(m0, mt0);
        const float mn1 = fmaxf(m1, mt1);
        const float al0 = __expf(m0 - mn0);
        const float al1 = __expf(m1 - mn1);
        float ls0 = 0.f, ls1 = 0.f;
#pragma unroll
        for (int j = 0; j < 8; j++) {
            s[j][0] = __expf(s[j][0] - mn0);
            s[j][1] = __expf(s[j][1] - mn0);
            s[j][2] = __expf(s[j][2] - mn1);
            s[j][3] = __expf(s[j][3] - mn1);
            ls0 += s[j][0] + s[j][1];
            ls1 += s[j][2] + s[j][3];
        }
        ls0 += __shfl_xor_sync(0xffffffffu, ls0, 1);
        ls0 += __shfl_xor_sync(0xffffffffu, ls0, 2);
        ls1 += __shfl_xor_sync(0xffffffffu, ls1, 1);
        ls1 += __shfl_xor_sync(0xffffffffu, ls1, 2);
        l0 = l0 * al0 + ls0;
        l1 = l1 * al1 + ls1;
        m0 = mn0;
        m1 = mn1;
#pragma unroll
        for (int j = 0; j < 8; j++) {
            o[j][0] *= al0; o[j][1] *= al0;
            o[j][2] *= al1; o[j][3] *= al1;
        }

        // ---- PV: O += P V. P C-frag packs directly into fp16 A-frag. ----
#pragma unroll
        for (int kk = 0; kk < 4; kk++) {    // kv k-steps of 16
            uint32_t a0 = pack_h2(s[2 * kk][0],     s[2 * kk][1]);
            uint32_t a1 = pack_h2(s[2 * kk][2],     s[2 * kk][3]);
            uint32_t a2 = pack_h2(s[2 * kk + 1][0], s[2 * kk + 1][1]);
            uint32_t a3 = pack_h2(s[2 * kk + 1][2], s[2 * kk + 1][3]);
#pragma unroll
            for (int c = 0; c < 4; c++) {   // d n-chunks of 16
                int kvrow = kk * 16 + ((lane >> 3) & 1) * 8 + (lane & 7);
                int dcol  = c * 16 + lhi8;
                uint32_t addr = vs_base + ((uint32_t)kvrow * 72u + dcol) * 2u;
                uint32_t b00, b01, b10, b11;
                ldsm_x4_trans(b00, b01, b10, b11, addr);
                mma_f16(o[2 * c][0], o[2 * c][1], o[2 * c][2], o[2 * c][3],
                        a0, a1, a2, a3, b00, b01);
                mma_f16(o[2 * c + 1][0], o[2 * c + 1][1], o[2 * c + 1][2], o[2 * c + 1][3],
                        a0, a1, a2, a3, b10, b11);
            }
        }
    }

    // ---- normalize + write ----
    const float il0 = 1.f / l0;
    const float il1 = 1.f / l1;
    float* op0 = out + (size_t)(b * S_ + row0) * C_ + h * 64;
    float* op1 = out + (size_t)(b * S_ + row0 + 8) * C_ + h * 64;
#pragma unroll
    for (int j2 = 0; j2 < 8; j2++) {
        int d0 = 8 * j2 + 2 * gc;
        float2 w0, w1;
        w0.x = o[j2][0] * il0; w0.y = o[j2][1] * il0;
        w1.x = o[j2][2] * il1; w1.y = o[j2][3] * il1;
        *(float2*)&op0[d0] = w0;
        *(float2*)&op1[d0] = w1;
    }
}

// ---------------------------------------------------------------------------
extern "C" void kernel_launch(void* const* d_in, const int* in_sizes, int n_in,
                              void* d_out, int out_size)
{
    const float* x      = (const float*)d_in[0];
    const float* qkv_w  = (const float*)d_in[1];
    const float* qkv_b  = (const float*)d_in[2];
    const float* proj_w = (const float*)d_in[3];
    const float* proj_b = (const float*)d_in[4];
    float* out = (float*)d_out;

    float *qkv, *att;
    cudaGetSymbolAddress((void**)&qkv, g_qkv);
    cudaGetSymbolAddress((void**)&att, g_att);

    // QKV: [8192,1024] x [3072,1024]^T
    gemm_f16<<<dim3(3072 / 128, M_ / 128), 256>>>(x, qkv_w, qkv_b, qkv,
                                                  M_, 3 * C_, C_);
    // Attention
    attn_f16<<<dim3(S_ / 64, B_ * H_), 128>>>(qkv, att);
    // Proj: [8192,1024] x [1024,1024]^T
    gemm_f16<<<dim3(C_ / 128, M_ / 128), 256>>>(att, proj_w, proj_b, out,
                                                M_, C_, C_);
}

// round 6
// speedup vs baseline: 16.4437x; 1.2614x over previous
#include <cuda_runtime.h>
#include <cuda_fp16.h>
#include <cstdint>

// Problem constants
#define B_  4
#define S_  2048
#define C_  1024
#define H_  16
#define D_  64
#define M_  (B_ * S_)      // 8192 tokens

// Scratch (allocation-free rule: __device__ globals)
__device__ __half g_xh  [(size_t)M_ * C_];        // x in fp16
__device__ __half g_wh  [3 * C_ * C_];            // qkv_w fp16
__device__ __half g_pwh [C_ * C_];                // proj_w fp16
__device__ __half g_qkvh[(size_t)M_ * 3 * C_];    // qkv activations fp16
__device__ __half g_atth[(size_t)M_ * C_];        // attention out fp16

// ---------------------------------------------------------------------------
// helpers
// ---------------------------------------------------------------------------
__device__ __forceinline__ uint32_t pack_h2(float x, float y) {
    __half2 h = __floats2half2_rn(x, y);
    return *reinterpret_cast<uint32_t*>(&h);
}

__device__ __forceinline__ void mma_f16(float& c0, float& c1, float& c2, float& c3,
                                        uint32_t a0, uint32_t a1, uint32_t a2, uint32_t a3,
                                        uint32_t b0, uint32_t b1) {
    asm volatile(
        "mma.sync.aligned.m16n8k16.row.col.f32.f16.f16.f32 "
        "{%0,%1,%2,%3}, {%4,%5,%6,%7}, {%8,%9}, {%0,%1,%2,%3};\n"
        : "+f"(c0), "+f"(c1), "+f"(c2), "+f"(c3)
        : "r"(a0), "r"(a1), "r"(a2), "r"(a3), "r"(b0), "r"(b1));
}

__device__ __forceinline__ void ldsm_x4(uint32_t& r0, uint32_t& r1, uint32_t& r2, uint32_t& r3,
                                        uint32_t addr) {
    asm volatile("ldmatrix.sync.aligned.m8n8.x4.shared.b16 {%0,%1,%2,%3}, [%4];\n"
                 : "=r"(r0), "=r"(r1), "=r"(r2), "=r"(r3) : "r"(addr));
}

__device__ __forceinline__ void ldsm_x4_trans(uint32_t& r0, uint32_t& r1, uint32_t& r2, uint32_t& r3,
                                              uint32_t addr) {
    asm volatile("ldmatrix.sync.aligned.m8n8.x4.trans.shared.b16 {%0,%1,%2,%3}, [%4];\n"
                 : "=r"(r0), "=r"(r1), "=r"(r2), "=r"(r3) : "r"(addr));
}

__device__ __forceinline__ void cp16(uint32_t dst, const void* src) {
    asm volatile("cp.async.cg.shared.global [%0], [%1], 16;\n" :: "r"(dst), "l"(src));
}

// ---------------------------------------------------------------------------
// f32 -> f16 conversion (8 elems / thread)
// ---------------------------------------------------------------------------
__global__ __launch_bounds__(256) void f2h(const float* __restrict__ s,
                                           __half* __restrict__ d, int n) {
    int i = (blockIdx.x * 256 + threadIdx.x) * 8;
    if (i < n) {
        float4 a = *(const float4*)(s + i);
        float4 b = *(const float4*)(s + i + 4);
        uint4 o;
        o.x = pack_h2(a.x, a.y);
        o.y = pack_h2(a.z, a.w);
        o.z = pack_h2(b.x, b.y);
        o.w = pack_h2(b.z, b.w);
        *(uint4*)(d + i) = o;
    }
}

// ---------------------------------------------------------------------------
// HMMA GEMM: C[m][n] = sum_k A[m][k]*W[n][k] + bias[n]
// A:[M,1024] f16 rm, W:[N,1024] f16 rm. CTA 128x128, 4 warps (2x2),
// warp tile 64x64, K-slab 32, cp.async double buffer.
// Smem stride 40 halves: conflict-free ldmatrix (20r mod 32 covers 8 groups).
// ---------------------------------------------------------------------------
template<typename OutT>
__global__ __launch_bounds__(128, 2) void gemm_hmma(
    const __half* __restrict__ A, const __half* __restrict__ W,
    const float* __restrict__ bias, OutT* __restrict__ Cmat, int N)
{
    __shared__ __half As[2][128][40];
    __shared__ __half Bs[2][128][40];

    const int tid  = threadIdx.x;
    const int lane = tid & 31;
    const int w    = tid >> 5;
    const int m_off = (w >> 1) * 64;
    const int n_off = (w & 1) * 64;
    const int brow = blockIdx.y * 128;
    const int bcol = blockIdx.x * 128;

    const int gr = lane >> 2;
    const int gc = lane & 3;
    const int lrow8 = ((lane >> 3) & 1) * 8 + (lane & 7);
    const int lhi8  = ((lane >> 4) & 1) * 8;
    const uint32_t as0 = (uint32_t)__cvta_generic_to_shared(&As[0][0][0]);
    const uint32_t bs0 = (uint32_t)__cvta_generic_to_shared(&Bs[0][0][0]);

    float acc[4][8][4];
#pragma unroll
    for (int a = 0; a < 4; a++)
#pragma unroll
        for (int n = 0; n < 8; n++)
#pragma unroll
            for (int c = 0; c < 4; c++) acc[a][n][c] = 0.f;

    // loader: 128 rows x 32 halves per matrix per slab = 512 x 16B chunks
    auto load_slab = [&](int k0, int s) {
#pragma unroll
        for (int i = 0; i < 4; i++) {
            int idx = i * 128 + tid;
            int rr = idx >> 2;
            int cc = (idx & 3) * 8;
            cp16(as0 + (uint32_t)(((s * 128 + rr) * 40 + cc) * 2),
                 A + (size_t)(brow + rr) * 1024 + k0 + cc);
            cp16(bs0 + (uint32_t)(((s * 128 + rr) * 40 + cc) * 2),
                 W + (size_t)(bcol + rr) * 1024 + k0 + cc);
        }
    };

    load_slab(0, 0);
    asm volatile("cp.async.commit_group;" ::: "memory");

    for (int k = 0; k < 32; k++) {
        const int buf = k & 1;
        if (k + 1 < 32) {
            load_slab((k + 1) * 32, (k + 1) & 1);
            asm volatile("cp.async.commit_group;" ::: "memory");
            asm volatile("cp.async.wait_group 1;" ::: "memory");
        } else {
            asm volatile("cp.async.wait_group 0;" ::: "memory");
        }
        __syncthreads();

#pragma unroll
        for (int kk = 0; kk < 2; kk++) {
            uint32_t af[4][4];
#pragma unroll
            for (int a = 0; a < 4; a++) {
                uint32_t addr = as0 +
                    (uint32_t)(((buf * 128 + m_off + 16 * a + lrow8) * 40 + kk * 16 + lhi8) * 2);
                ldsm_x4(af[a][0], af[a][1], af[a][2], af[a][3], addr);
            }
            uint32_t bf[8][2];
#pragma unroll
            for (int c = 0; c < 4; c++) {
                int nrow = n_off + c * 16 + lhi8 + (lane & 7);
                int kcol = kk * 16 + ((lane >> 3) & 1) * 8;
                uint32_t addr = bs0 + (uint32_t)(((buf * 128 + nrow) * 40 + kcol) * 2);
                ldsm_x4(bf[2 * c][0], bf[2 * c][1], bf[2 * c + 1][0], bf[2 * c + 1][1], addr);
            }
#pragma unroll
            for (int a = 0; a < 4; a++)
#pragma unroll
                for (int n = 0; n < 8; n++)
                    mma_f16(acc[a][n][0], acc[a][n][1], acc[a][n][2], acc[a][n][3],
                            af[a][0], af[a][1], af[a][2], af[a][3],
                            bf[n][0], bf[n][1]);
        }
        __syncthreads();
    }

    // epilogue
#pragma unroll
    for (int a = 0; a < 4; a++) {
        int r0 = brow + m_off + 16 * a + gr;
#pragma unroll
        for (int n = 0; n < 8; n++) {
            int col = bcol + n_off + 8 * n + 2 * gc;
            float b0 = bias[col], b1 = bias[col + 1];
            if constexpr (sizeof(OutT) == 4) {
                float* p0 = (float*)Cmat + (size_t)r0 * N + col;
                float* p1 = (float*)Cmat + (size_t)(r0 + 8) * N + col;
                float2 o0, o1;
                o0.x = acc[a][n][0] + b0; o0.y = acc[a][n][1] + b1;
                o1.x = acc[a][n][2] + b0; o1.y = acc[a][n][3] + b1;
                *(float2*)p0 = o0;
                *(float2*)p1 = o1;
            } else {
                __half* p0 = (__half*)Cmat + (size_t)r0 * N + col;
                __half* p1 = (__half*)Cmat + (size_t)(r0 + 8) * N + col;
                *(uint32_t*)p0 = pack_h2(acc[a][n][0] + b0, acc[a][n][1] + b1);
                *(uint32_t*)p1 = pack_h2(acc[a][n][2] + b0, acc[a][n][3] + b1);
            }
        }
    }
}

// ---------------------------------------------------------------------------
// Flash attention (causal), fp16 in/out. Grid (16, 64), block 128.
// Q tile 128 rows/CTA; warp w owns rows 32w..32w+31 (mi=0,1 sub-tiles of 16).
// K/V tile 64 rows; Q-frags hoisted; P C-frag == fp16 A-frag (pack only).
// ---------------------------------------------------------------------------
__global__ __launch_bounds__(128, 2) void attn_f16(
    const __half* __restrict__ qkv, __half* __restrict__ out)
{
    __shared__ __half Ks[64][72];
    __shared__ __half Vs[64][72];

    const int qblk = gridDim.x - 1 - blockIdx.x;   // heavy blocks first
    const int bh   = blockIdx.y;
    const int b    = bh >> 4;
    const int h    = bh & 15;

    const int tid  = threadIdx.x;
    const int lane = tid & 31;
    const int w    = tid >> 5;
    const int gr   = lane >> 2;
    const int gc   = lane & 3;
    const int lrow8 = ((lane >> 3) & 1) * 8 + (lane & 7);
    const int lhi8  = ((lane >> 4) & 1) * 8;
    const uint32_t ks_base = (uint32_t)__cvta_generic_to_shared(&Ks[0][0]);
    const uint32_t vs_base = (uint32_t)__cvta_generic_to_shared(&Vs[0][0]);

    const __half* base = qkv + (size_t)b * S_ * 3 * C_;

    // ---- Q prologue: two 64-row phases through Ks; hoist A-frags ----
    uint32_t qf[2][4][4];
#pragma unroll
    for (int p = 0; p < 2; p++) {
#pragma unroll
        for (int i = 0; i < 4; i++) {
            int idx = i * 128 + tid;
            int r = idx >> 3;
            int c8 = (idx & 7) * 8;
            *(uint4*)&Ks[r][c8] = *(const uint4*)(
                base + (size_t)(qblk * 128 + p * 64 + r) * (3 * C_) + h * 64 + c8);
        }
        __syncthreads();
        if ((w >> 1) == p) {
            int lr = (w & 1) * 32;
#pragma unroll
            for (int mi = 0; mi < 2; mi++)
#pragma unroll
                for (int kk = 0; kk < 4; kk++) {
                    uint32_t addr = ks_base +
                        ((uint32_t)(lr + 16 * mi + lrow8) * 72u + kk * 16 + lhi8) * 2u;
                    ldsm_x4(qf[mi][kk][0], qf[mi][kk][1], qf[mi][kk][2], qf[mi][kk][3], addr);
                }
        }
        __syncthreads();
    }

    float o[2][8][4];
#pragma unroll
    for (int mi = 0; mi < 2; mi++)
#pragma unroll
        for (int j = 0; j < 8; j++)
#pragma unroll
            for (int c = 0; c < 4; c++) o[mi][j][c] = 0.f;
    float mm[2][2] = {{-1e30f, -1e30f}, {-1e30f, -1e30f}};
    float ll[2][2] = {{0.f, 0.f}, {0.f, 0.f}};

    const int nkv = 2 * qblk + 2;

    for (int kvb = 0; kvb < nkv; kvb++) {
        __syncthreads();
#pragma unroll
        for (int i = 0; i < 4; i++) {
            int idx = i * 128 + tid;
            int r = idx >> 3;
            int c8 = (idx & 7) * 8;
            const __half* kp = base + (size_t)(kvb * 64 + r) * (3 * C_) + C_ + h * 64 + c8;
            const __half* vp = base + (size_t)(kvb * 64 + r) * (3 * C_) + 2 * C_ + h * 64 + c8;
            *(uint4*)&Ks[r][c8] = *(const uint4*)kp;
            *(uint4*)&Vs[r][c8] = *(const uint4*)vp;
        }
        __syncthreads();

        // ---- S = Q K^T (32x64 per warp) ----
        float s[2][8][4];
#pragma unroll
        for (int mi = 0; mi < 2; mi++)
#pragma unroll
            for (int j = 0; j < 8; j++)
#pragma unroll
                for (int c = 0; c < 4; c++) s[mi][j][c] = 0.f;

#pragma unroll
        for (int kk = 0; kk < 4; kk++) {
#pragma unroll
            for (int c = 0; c < 4; c++) {
                int nrow = c * 16 + lhi8 + (lane & 7);
                int kcol = kk * 16 + ((lane >> 3) & 1) * 8;
                uint32_t addr = ks_base + ((uint32_t)nrow * 72u + kcol) * 2u;
                uint32_t b00, b01, b10, b11;
                ldsm_x4(b00, b01, b10, b11, addr);
#pragma unroll
                for (int mi = 0; mi < 2; mi++) {
                    mma_f16(s[mi][2 * c][0], s[mi][2 * c][1], s[mi][2 * c][2], s[mi][2 * c][3],
                            qf[mi][kk][0], qf[mi][kk][1], qf[mi][kk][2], qf[mi][kk][3], b00, b01);
                    mma_f16(s[mi][2 * c + 1][0], s[mi][2 * c + 1][1],
                            s[mi][2 * c + 1][2], s[mi][2 * c + 1][3],
                            qf[mi][kk][0], qf[mi][kk][1], qf[mi][kk][2], qf[mi][kk][3], b10, b11);
                }
            }
        }
#pragma unroll
        for (int mi = 0; mi < 2; mi++)
#pragma unroll
            for (int j = 0; j < 8; j++)
#pragma unroll
                for (int c = 0; c < 4; c++) s[mi][j][c] *= 0.125f;

        // ---- causal mask: only the last two kv tiles can cross the diagonal ----
        if (kvb >= 2 * qblk) {
#pragma unroll
            for (int mi = 0; mi < 2; mi++) {
                int rowm = qblk * 128 + 32 * w + 16 * mi + gr;
#pragma unroll
                for (int j = 0; j < 8; j++) {
                    int colb = kvb * 64 + 8 * j + 2 * gc;
                    if (colb     > rowm)     s[mi][j][0] = -1e30f;
                    if (colb + 1 > rowm)     s[mi][j][1] = -1e30f;
                    if (colb     > rowm + 8) s[mi][j][2] = -1e30f;
                    if (colb + 1 > rowm + 8) s[mi][j][3] = -1e30f;
                }
            }
        }

        // ---- online softmax (per mi, two row-halves each) ----
#pragma unroll
        for (int mi = 0; mi < 2; mi++) {
            float mt0 = -1e30f, mt1 = -1e30f;
#pragma unroll
            for (int j = 0; j < 8; j++) {
                mt0 = fmaxf(mt0, fmaxf(s[mi][j][0], s[mi][j][1]));
                mt1 = fmaxf(mt1, fmaxf(s[mi][j][2], s[mi][j][3]));
            }
            mt0 = fmaxf(mt0, __shfl_xor_sync(0xffffffffu, mt0, 1));
            mt0 = fmaxf(mt0, __shfl_xor_sync(0xffffffffu, mt0, 2));
            mt1 = fmaxf(mt1, __shfl_xor_sync(0xffffffffu, mt1, 1));
            mt1 = fmaxf(mt1, __shfl_xor_sync(0xffffffffu, mt1, 2));

            const float mn0 = fmaxf(mm[mi][0], mt0);
            const float mn1 = fmaxf(mm[mi][1], mt1);
            const float al0 = __expf(mm[mi][0] - mn0);
            const float al1 = __expf(mm[mi][1] - mn1);
            float ls0 = 0.f, ls1 = 0.f;
#pragma unroll
            for (int j = 0; j < 8; j++) {
                s[mi][j][0] = __expf(s[mi][j][0] - mn0);
                s[mi][j][1] = __expf(s[mi][j][1] - mn0);
                s[mi][j][2] = __expf(s[mi][j][2] - mn1);
                s[mi][j][3] = __expf(s[mi][j][3] - mn1);
                ls0 += s[mi][j][0] + s[mi][j][1];
                ls1 += s[mi][j][2] + s[mi][j][3];
            }
            ls0 += __shfl_xor_sync(0xffffffffu, ls0, 1);
            ls0 += __shfl_xor_sync(0xffffffffu, ls0, 2);
            ls1 += __shfl_xor_sync(0xffffffffu, ls1, 1);
            ls1 += __shfl_xor_sync(0xffffffffu, ls1, 2);
            ll[mi][0] = ll[mi][0] * al0 + ls0;
            ll[mi][1] = ll[mi][1] * al1 + ls1;
            mm[mi][0] = mn0;
            mm[mi][1] = mn1;
#pragma unroll
            for (int j = 0; j < 8; j++) {
                o[mi][j][0] *= al0; o[mi][j][1] *= al0;
                o[mi][j][2] *= al1; o[mi][j][3] *= al1;
            }
        }

        // ---- PV: V-frags shared across both mi ----
#pragma unroll
        for (int kk = 0; kk < 4; kk++) {
            uint32_t pa[2][4];
#pragma unroll
            for (int mi = 0; mi < 2; mi++) {
                pa[mi][0] = pack_h2(s[mi][2 * kk][0],     s[mi][2 * kk][1]);
                pa[mi][1] = pack_h2(s[mi][2 * kk][2],     s[mi][2 * kk][3]);
                pa[mi][2] = pack_h2(s[mi][2 * kk + 1][0], s[mi][2 * kk + 1][1]);
                pa[mi][3] = pack_h2(s[mi][2 * kk + 1][2], s[mi][2 * kk + 1][3]);
            }
#pragma unroll
            for (int c = 0; c < 4; c++) {
                int kvrow = kk * 16 + ((lane >> 3) & 1) * 8 + (lane & 7);
                int dcol  = c * 16 + lhi8;
                uint32_t addr = vs_base + ((uint32_t)kvrow * 72u + dcol) * 2u;
                uint32_t b00, b01, b10, b11;
                ldsm_x4_trans(b00, b01, b10, b11, addr);
#pragma unroll
                for (int mi = 0; mi < 2; mi++) {
                    mma_f16(o[mi][2 * c][0], o[mi][2 * c][1], o[mi][2 * c][2], o[mi][2 * c][3],
                            pa[mi][0], pa[mi][1], pa[mi][2], pa[mi][3], b00, b01);
                    mma_f16(o[mi][2 * c + 1][0], o[mi][2 * c + 1][1],
                            o[mi][2 * c + 1][2], o[mi][2 * c + 1][3],
                            pa[mi][0], pa[mi][1], pa[mi][2], pa[mi][3], b10, b11);
                }
            }
        }
    }

    // ---- normalize + write fp16 ----
#pragma unroll
    for (int mi = 0; mi < 2; mi++) {
        const int row0 = qblk * 128 + 32 * w + 16 * mi + gr;
        const float il0 = 1.f / ll[mi][0];
        const float il1 = 1.f / ll[mi][1];
        __half* op0 = out + (size_t)(b * S_ + row0) * C_ + h * 64;
        __half* op1 = out + (size_t)(b * S_ + row0 + 8) * C_ + h * 64;
#pragma unroll
        for (int j2 = 0; j2 < 8; j2++) {
            int d0 = 8 * j2 + 2 * gc;
            *(uint32_t*)&op0[d0] = pack_h2(o[mi][j2][0] * il0, o[mi][j2][1] * il0);
            *(uint32_t*)&op1[d0] = pack_h2(o[mi][j2][2] * il1, o[mi][j2][3] * il1);
        }
    }
}

// ---------------------------------------------------------------------------
extern "C" void kernel_launch(void* const* d_in, const int* in_sizes, int n_in,
                              void* d_out, int out_size)
{
    const float* x      = (const float*)d_in[0];
    const float* qkv_w  = (const float*)d_in[1];
    const float* qkv_b  = (const float*)d_in[2];
    const float* proj_w = (const float*)d_in[3];
    const float* proj_b = (const float*)d_in[4];
    float* out = (float*)d_out;

    __half *xh, *wh, *pwh, *qkvh, *atth;
    cudaGetSymbolAddress((void**)&xh,   g_xh);
    cudaGetSymbolAddress((void**)&wh,   g_wh);
    cudaGetSymbolAddress((void**)&pwh,  g_pwh);
    cudaGetSymbolAddress((void**)&qkvh, g_qkvh);
    cudaGetSymbolAddress((void**)&atth, g_atth);

    // fp16 conversions
    f2h<<<(M_ * C_) / 2048, 256>>>(x, xh, M_ * C_);
    f2h<<<(3 * C_ * C_) / 2048, 256>>>(qkv_w, wh, 3 * C_ * C_);
    f2h<<<(C_ * C_) / 2048, 256>>>(proj_w, pwh, C_ * C_);

    // QKV: [8192,1024] x [3072,1024]^T -> fp16
    gemm_hmma<__half><<<dim3(3072 / 128, M_ / 128), 128>>>(xh, wh, qkv_b, qkvh, 3 * C_);
    // Attention (fp16 in/out), Q tile 128
    attn_f16<<<dim3(S_ / 128, B_ * H_), 128>>>(qkvh, atth);
    // Proj: [8192,1024] x [1024,1024]^T -> fp32 out
    gemm_hmma<float><<<dim3(C_ / 128, M_ / 128), 128>>>(atth, pwh, proj_b, out, C_);
}